// round 2
// baseline (speedup 1.0000x reference)
#include <cuda_runtime.h>
#include <cuda_bf16.h>
#include <math.h>

// Problem constants
#define B     32
#define CIN   512
#define HW    4096          // 64*64
#define MID   32            // 512/16
#define COUT  512

// Scratch (no cudaMalloc allowed)
__device__ float g_pooled[B * CIN];   // [B, CIN] means

// ---------------------------------------------------------------------------
// Kernel 1: global average pool.
// One CTA per (b, c) row: 4096 contiguous floats. 256 threads, each loads
// 4 x float4 (16 floats), tree-reduce, write mean.
// ---------------------------------------------------------------------------
__global__ __launch_bounds__(256) void se_pool_kernel(const float* __restrict__ x) {
    const int row = blockIdx.x;                 // 0 .. B*CIN-1
    const float4* __restrict__ p =
        reinterpret_cast<const float4*>(x + (size_t)row * HW);
    const int tid = threadIdx.x;

    // 1024 float4 per row; 256 threads -> 4 each (stride 256 for coalescing)
    float4 v0 = p[tid];
    float4 v1 = p[tid + 256];
    float4 v2 = p[tid + 512];
    float4 v3 = p[tid + 768];

    float s = (v0.x + v0.y) + (v0.z + v0.w)
            + (v1.x + v1.y) + (v1.z + v1.w)
            + (v2.x + v2.y) + (v2.z + v2.w)
            + (v3.x + v3.y) + (v3.z + v3.w);

    // warp reduce
    #pragma unroll
    for (int off = 16; off > 0; off >>= 1)
        s += __shfl_xor_sync(0xFFFFFFFFu, s, off);

    __shared__ float warp_sums[8];
    const int lane = tid & 31;
    const int wid  = tid >> 5;
    if (lane == 0) warp_sums[wid] = s;
    __syncthreads();

    if (wid == 0) {
        float t = (lane < 8) ? warp_sums[lane] : 0.0f;
        #pragma unroll
        for (int off = 4; off > 0; off >>= 1)
            t += __shfl_xor_sync(0xFFFFFFFFu, t, off);
        if (lane == 0)
            g_pooled[row] = t * (1.0f / (float)HW);
    }
}

// ---------------------------------------------------------------------------
// Kernel 2: FC bottleneck + ReLU, FC expansion + sigmoid.
// One CTA per batch row b. 512 threads.
//   Phase 1: 16 warps, each computes 2 mids (m = wid*2 + i): 512-dot via
//            lane-strided partials + shuffle reduce -> h[m] = relu(. + b1[m]).
//   Phase 2: thread o computes sigmoid(sum_m h[m]*w2[o*MID+m] + b2[o]).
// ---------------------------------------------------------------------------
__global__ __launch_bounds__(512) void se_fc_kernel(
    const float* __restrict__ w1, const float* __restrict__ b1,
    const float* __restrict__ w2, const float* __restrict__ b2,
    float* __restrict__ out)
{
    const int b   = blockIdx.x;
    const int tid = threadIdx.x;
    const int lane = tid & 31;
    const int wid  = tid >> 5;

    __shared__ float s_pooled[CIN];
    __shared__ float s_h[MID];

    // load pooled row into smem
    s_pooled[tid] = g_pooled[b * CIN + tid];
    __syncthreads();

    // Phase 1: each of 16 warps computes 2 mid channels
    #pragma unroll
    for (int i = 0; i < 2; i++) {
        const int m = wid * 2 + i;            // 0..31
        const float* __restrict__ wrow = w1 + (size_t)m * CIN;
        float acc = 0.0f;
        #pragma unroll
        for (int k = lane; k < CIN; k += 32)
            acc = fmaf(s_pooled[k], wrow[k], acc);
        #pragma unroll
        for (int off = 16; off > 0; off >>= 1)
            acc += __shfl_xor_sync(0xFFFFFFFFu, acc, off);
        if (lane == 0) {
            float hv = acc + b1[m];
            s_h[m] = hv > 0.0f ? hv : 0.0f;
        }
    }
    __syncthreads();

    // Phase 2: thread tid computes output channel tid
    const float* __restrict__ w2row = w2 + (size_t)tid * MID;
    float acc = b2[tid];
    #pragma unroll
    for (int m = 0; m < MID; m++)
        acc = fmaf(s_h[m], w2row[m], acc);
    out[b * COUT + tid] = 1.0f / (1.0f + __expf(-acc));
}

// ---------------------------------------------------------------------------
extern "C" void kernel_launch(void* const* d_in, const int* in_sizes, int n_in,
                              void* d_out, int out_size) {
    const float* x  = (const float*)d_in[0];
    const float* w1 = (const float*)d_in[1];
    const float* b1 = (const float*)d_in[2];
    const float* w2 = (const float*)d_in[3];
    const float* b2 = (const float*)d_in[4];
    float* out = (float*)d_out;

    se_pool_kernel<<<B * CIN, 256>>>(x);
    se_fc_kernel<<<B, 512>>>(w1, b1, w2, b2, out);
}

// round 3
// speedup vs baseline: 1.1504x; 1.1504x over previous
#include <cuda_runtime.h>
#include <cuda_bf16.h>
#include <math.h>

// Problem constants
#define B     32
#define CIN   512
#define HW    4096          // 64*64
#define MID   32            // 512/16
#define COUT  512

// Scratch (no cudaMalloc allowed)
__device__ float g_pooled[B * CIN];   // [B, CIN] means

// ---------------------------------------------------------------------------
// Kernel 1: global average pool.  (unchanged — at HBM roofline, ~6.9 TB/s)
// One CTA per (b, c) row: 4096 contiguous floats. 256 threads, each loads
// 4 x float4 (16 floats), tree-reduce, write mean.
// ---------------------------------------------------------------------------
__global__ __launch_bounds__(256) void se_pool_kernel(const float* __restrict__ x) {
    const int row = blockIdx.x;                 // 0 .. B*CIN-1
    const float4* __restrict__ p =
        reinterpret_cast<const float4*>(x + (size_t)row * HW);
    const int tid = threadIdx.x;

    float4 v0 = p[tid];
    float4 v1 = p[tid + 256];
    float4 v2 = p[tid + 512];
    float4 v3 = p[tid + 768];

    float s = (v0.x + v0.y) + (v0.z + v0.w)
            + (v1.x + v1.y) + (v1.z + v1.w)
            + (v2.x + v2.y) + (v2.z + v2.w)
            + (v3.x + v3.y) + (v3.z + v3.w);

    #pragma unroll
    for (int off = 16; off > 0; off >>= 1)
        s += __shfl_xor_sync(0xFFFFFFFFu, s, off);

    __shared__ float warp_sums[8];
    const int lane = tid & 31;
    const int wid  = tid >> 5;
    if (lane == 0) warp_sums[wid] = s;
    __syncthreads();

    if (wid == 0) {
        float t = (lane < 8) ? warp_sums[lane] : 0.0f;
        #pragma unroll
        for (int off = 4; off > 0; off >>= 1)
            t += __shfl_xor_sync(0xFFFFFFFFu, t, off);
        if (lane == 0)
            g_pooled[row] = t * (1.0f / (float)HW);
    }
}

// ---------------------------------------------------------------------------
// Kernel 2: FC bottleneck + ReLU, FC expansion + sigmoid.
// One CTA per batch row b. 512 threads (16 warps).
//   Phase 1: warp w computes mids {2w, 2w+1} via lane-strided dot + reduce.
//   Phase 2: warp w owns outputs [32w, 32w+32). For each output i the warp
//            loads w2[(32w+i)*32 + lane]  -- COALESCED (1 line / LDG) --
//            multiplies by s_h[lane], butterfly-reduces, lane i keeps result.
// ---------------------------------------------------------------------------
__global__ __launch_bounds__(512) void se_fc_kernel(
    const float* __restrict__ w1, const float* __restrict__ b1,
    const float* __restrict__ w2, const float* __restrict__ b2,
    float* __restrict__ out)
{
    const int b    = blockIdx.x;
    const int tid  = threadIdx.x;
    const int lane = tid & 31;
    const int wid  = tid >> 5;

    __shared__ float s_pooled[CIN];
    __shared__ float s_h[MID];

    s_pooled[tid] = g_pooled[b * CIN + tid];
    __syncthreads();

    // Phase 1: each of 16 warps computes 2 mid channels (coalesced w1 reads)
    #pragma unroll
    for (int i = 0; i < 2; i++) {
        const int m = wid * 2 + i;            // 0..31
        const float* __restrict__ wrow = w1 + (size_t)m * CIN;
        float acc = 0.0f;
        #pragma unroll
        for (int k = lane; k < CIN; k += 32)
            acc = fmaf(s_pooled[k], wrow[k], acc);
        #pragma unroll
        for (int off = 16; off > 0; off >>= 1)
            acc += __shfl_xor_sync(0xFFFFFFFFu, acc, off);
        if (lane == 0) {
            float hv = acc + b1[m];
            s_h[m] = hv > 0.0f ? hv : 0.0f;
        }
    }
    __syncthreads();

    // Phase 2: warp-tile, coalesced w2 reads
    const int o_base = wid * 32;
    const float hv   = s_h[lane];             // h[m] for m = lane
    float res = 0.0f;

    #pragma unroll
    for (int i = 0; i < 32; i++) {
        // w2 row (o_base + i), column = lane  -> consecutive lanes consecutive
        float r = w2[(size_t)(o_base + i) * MID + lane];
        float p = r * hv;
        #pragma unroll
        for (int off = 16; off > 0; off >>= 1)
            p += __shfl_xor_sync(0xFFFFFFFFu, p, off);
        if (lane == i) res = p;               // lane i keeps output o_base+i
    }

    const int o = o_base + lane;
    float acc = res + b2[o];
    out[b * COUT + o] = 1.0f / (1.0f + __expf(-acc));
}

// ---------------------------------------------------------------------------
extern "C" void kernel_launch(void* const* d_in, const int* in_sizes, int n_in,
                              void* d_out, int out_size) {
    const float* x  = (const float*)d_in[0];
    const float* w1 = (const float*)d_in[1];
    const float* b1 = (const float*)d_in[2];
    const float* w2 = (const float*)d_in[3];
    const float* b2 = (const float*)d_in[4];
    float* out = (float*)d_out;

    se_pool_kernel<<<B * CIN, 256>>>(x);
    se_fc_kernel<<<B, 512>>>(w1, b1, w2, b2, out);
}